// round 2
// baseline (speedup 1.0000x reference)
#include <cuda_runtime.h>
#include <math.h>

#define NN     65536
#define KNN    12
#define WID    256
#define GW     192
#define FFD    48
#define CONDD  64
#define DEPTHL 7
#define GL     4

// ---------------- scratch (static device allocations; allowed) ----------------
__device__ float4 g_pts4[NN];
__device__ int    g_knn[NN * KNN];
__device__ float  g_ff[NN * FFD];
__device__ float  g_h0[NN * WID];
__device__ float  g_gA[NN * GW];
__device__ float  g_gB[NN * GW];
__device__ float  g_agg[NN * GW];
__device__ float  g_hA[NN * WID];
__device__ float  g_hB[NN * WID];
__device__ float  g_film[DEPTHL * 2 * WID];

// ---------------- prep: pts4 (x,y,z,|x|^2) + fourier features ----------------
__global__ void prep_kernel(const float* __restrict__ x, const float* __restrict__ Bf) {
    __shared__ float Bs[72];
    if (threadIdx.x < 72) Bs[threadIdx.x] = Bf[threadIdx.x];
    __syncthreads();
    int n = blockIdx.x * blockDim.x + threadIdx.x;
    if (n >= NN) return;
    float x0 = x[n * 3 + 0], x1 = x[n * 3 + 1], x2 = x[n * 3 + 2];
    g_pts4[n] = make_float4(x0, x1, x2, x0 * x0 + x1 * x1 + x2 * x2);
#pragma unroll
    for (int sm = 0; sm < 24; sm++) {      // s*8+m, B[s][d][m] flat = s*24 + d*8 + m
        int s = sm >> 3, m = sm & 7;
        float p = x0 * Bs[s * 24 + 0 * 8 + m]
                + x1 * Bs[s * 24 + 1 * 8 + m]
                + x2 * Bs[s * 24 + 2 * 8 + m];
        g_ff[n * FFD + sm]      = sinf(p);
        g_ff[n * FFD + 24 + sm] = cosf(p);
    }
}

// ---------------- exact kNN: one thread per query, SMEM-staged candidates ----------------
#define KTILE 1024
__global__ void knn_kernel() {
    __shared__ float4 sm[KTILE];
    int q = blockIdx.x * blockDim.x + threadIdx.x;
    float4 me = g_pts4[q];
    float m2x = -2.f * me.x, m2y = -2.f * me.y, m2z = -2.f * me.z;
    float dist[KNN];
    int   nidx[KNN];
#pragma unroll
    for (int i = 0; i < KNN; i++) { dist[i] = 3.0e38f; nidx[i] = 0; }

    for (int base = 0; base < NN; base += KTILE) {
        __syncthreads();
#pragma unroll
        for (int i = 0; i < KTILE / 128; i++)
            sm[threadIdx.x + 128 * i] = g_pts4[base + threadIdx.x + 128 * i];
        __syncthreads();
#pragma unroll 4
        for (int j = 0; j < KTILE; j++) {
            float4 c = sm[j];
            float d = c.w + me.w;
            d = fmaf(m2x, c.x, d);
            d = fmaf(m2y, c.y, d);
            d = fmaf(m2z, c.z, d);
            int cj = base + j;
            if (d < dist[KNN - 1] && cj != q) {
                dist[KNN - 1] = d; nidx[KNN - 1] = cj;
#pragma unroll
                for (int s = KNN - 1; s > 0; --s) {
                    if (dist[s] < dist[s - 1]) {    // strict < => stable tie-break (matches top_k)
                        float td = dist[s]; dist[s] = dist[s - 1]; dist[s - 1] = td;
                        int   ti = nidx[s]; nidx[s] = nidx[s - 1]; nidx[s - 1] = ti;
                    }
                }
            }
        }
    }
#pragma unroll
    for (int i = 0; i < KNN; i++) g_knn[q * KNN + i] = nidx[i];
}

// ---------------- FiLM params: gamma/beta for all 7 layers ----------------
__global__ void film_kernel(const float* __restrict__ cond,
                            const float* __restrict__ Wf_g, const float* __restrict__ bf_g,
                            const float* __restrict__ Wf_b, const float* __restrict__ bf_b) {
    __shared__ float cs[CONDD];
    if (threadIdx.x < CONDD) cs[threadIdx.x] = cond[threadIdx.x];
    __syncthreads();
    int t = blockIdx.x * blockDim.x + threadIdx.x;
    if (t >= DEPTHL * 2 * WID) return;
    int l = t / (2 * WID);
    int r = t % (2 * WID);
    int isb = r >> 8;            // 0 = gamma, 1 = beta
    int n = r & (WID - 1);
    const float* Wt = isb ? Wf_b : Wf_g;
    const float* bt = isb ? bf_b : bf_g;
    float s = bt[l * WID + n];
#pragma unroll 8
    for (int d = 0; d < CONDD; d++) s += cs[d] * Wt[(l * CONDD + d) * WID + n];
    g_film[l * 2 * WID + isb * WID + n] = s;
}

// ---------------- gather-mean over 12 neighbors ----------------
__global__ void agg_kernel(const float* __restrict__ gfeat, float* __restrict__ agg) {
    int n = blockIdx.x;
    int f = threadIdx.x;        // blockDim = GW
    __shared__ int idx[KNN];
    if (f < KNN) idx[f] = g_knn[n * KNN + f];
    __syncthreads();
    float s = 0.f;
#pragma unroll
    for (int k = 0; k < KNN; k++) s += gfeat[idx[k] * GW + f];
    agg[n * GW + f] = s * (1.f / (float)KNN);
}

// ---------------- generic tiled GEMM with fused epilogue ----------------
// C = ep( A@Wt [+ A2@W2] + bias ), ep: optional FiLM (1+gamma)*v+beta, optional SiLU,
// optional post-activation residual add.
#define BM 64
#define BN 64
#define BK 16
__global__ void gemm_ep(const float* __restrict__ A,  const float* __restrict__ Wt,
                        const float* __restrict__ A2, const float* __restrict__ W2,
                        const float* __restrict__ bias,
                        const float* __restrict__ gamma, const float* __restrict__ beta,
                        const float* __restrict__ res,
                        float* __restrict__ C,
                        int M, int Kd, int Nd, int doSilu) {
    __shared__ float As[BK][BM + 4];
    __shared__ float Bs[BK][BN];
    int bm = blockIdx.y * BM, bn = blockIdx.x * BN;
    int t = threadIdx.x;
    int tx = t & 15, ty = t >> 4;
    float acc[4][4];
#pragma unroll
    for (int i = 0; i < 4; i++)
#pragma unroll
        for (int j = 0; j < 4; j++) acc[i][j] = 0.f;

    for (int pass = 0; pass < 2; pass++) {
        const float* Ap = pass ? A2 : A;
        const float* Wp = pass ? W2 : Wt;
        if (Ap == nullptr) break;
        for (int k0 = 0; k0 < Kd; k0 += BK) {
            // load A tile (64 rows x 16 k), store transposed
#pragma unroll
            for (int i = 0; i < 4; i++) {
                int lr = (t >> 4) + 16 * i;
                As[t & 15][lr] = Ap[(size_t)(bm + lr) * Kd + k0 + (t & 15)];
            }
            // load W tile (16 k x 64 n)
#pragma unroll
            for (int i = 0; i < 4; i++) {
                int lk = (t >> 6) + 4 * i;
                Bs[lk][t & 63] = Wp[(size_t)(k0 + lk) * Nd + bn + (t & 63)];
            }
            __syncthreads();
#pragma unroll
            for (int kk = 0; kk < BK; kk++) {
                float4 a = *reinterpret_cast<const float4*>(&As[kk][ty * 4]);
                float4 b = *reinterpret_cast<const float4*>(&Bs[kk][tx * 4]);
                acc[0][0] = fmaf(a.x, b.x, acc[0][0]); acc[0][1] = fmaf(a.x, b.y, acc[0][1]);
                acc[0][2] = fmaf(a.x, b.z, acc[0][2]); acc[0][3] = fmaf(a.x, b.w, acc[0][3]);
                acc[1][0] = fmaf(a.y, b.x, acc[1][0]); acc[1][1] = fmaf(a.y, b.y, acc[1][1]);
                acc[1][2] = fmaf(a.y, b.z, acc[1][2]); acc[1][3] = fmaf(a.y, b.w, acc[1][3]);
                acc[2][0] = fmaf(a.z, b.x, acc[2][0]); acc[2][1] = fmaf(a.z, b.y, acc[2][1]);
                acc[2][2] = fmaf(a.z, b.z, acc[2][2]); acc[2][3] = fmaf(a.z, b.w, acc[2][3]);
                acc[3][0] = fmaf(a.w, b.x, acc[3][0]); acc[3][1] = fmaf(a.w, b.y, acc[3][1]);
                acc[3][2] = fmaf(a.w, b.z, acc[3][2]); acc[3][3] = fmaf(a.w, b.w, acc[3][3]);
            }
            __syncthreads();
        }
    }

#pragma unroll
    for (int i = 0; i < 4; i++) {
        int m = bm + ty * 4 + i;
#pragma unroll
        for (int j = 0; j < 4; j++) {
            int n = bn + tx * 4 + j;
            float v = acc[i][j];
            if (bias)  v += bias[n];
            if (gamma) v = v * (1.f + gamma[n]) + beta[n];
            if (doSilu) v = v / (1.f + expf(-v));
            if (res)   v += res[(size_t)m * Nd + n];
            C[(size_t)m * Nd + n] = v;
        }
    }
}

// ---------------- final projection: (h @ W_out + b_out) * 0.01 ----------------
__global__ void out_kernel(const float* __restrict__ h,
                           const float* __restrict__ Wout, const float* __restrict__ bout,
                           float* __restrict__ out) {
    int gt = blockIdx.x * blockDim.x + threadIdx.x;
    int n = gt >> 5;
    int lane = gt & 31;
    if (n >= NN) return;
    float a0 = 0.f, a1 = 0.f, a2 = 0.f;
#pragma unroll
    for (int k = lane; k < WID; k += 32) {
        float hv = h[(size_t)n * WID + k];
        a0 = fmaf(hv, Wout[k * 3 + 0], a0);
        a1 = fmaf(hv, Wout[k * 3 + 1], a1);
        a2 = fmaf(hv, Wout[k * 3 + 2], a2);
    }
#pragma unroll
    for (int off = 16; off > 0; off >>= 1) {
        a0 += __shfl_down_sync(0xffffffffu, a0, off);
        a1 += __shfl_down_sync(0xffffffffu, a1, off);
        a2 += __shfl_down_sync(0xffffffffu, a2, off);
    }
    if (lane == 0) {
        out[n * 3 + 0] = (a0 + bout[0]) * 0.01f;
        out[n * 3 + 1] = (a1 + bout[1]) * 0.01f;
        out[n * 3 + 2] = (a2 + bout[2]) * 0.01f;
    }
}

// ---------------- host launcher ----------------
extern "C" void kernel_launch(void* const* d_in, const int* in_sizes, int n_in,
                              void* d_out, int out_size) {
    const float* x      = (const float*)d_in[0];
    const float* cond   = (const float*)d_in[1];
    const float* Bf     = (const float*)d_in[2];
    const float* W_in   = (const float*)d_in[3];
    const float* b_in   = (const float*)d_in[4];
    const float* Wg_in  = (const float*)d_in[5];
    const float* bg_in  = (const float*)d_in[6];
    const float* Ws     = (const float*)d_in[7];
    const float* Wn     = (const float*)d_in[8];
    const float* bg     = (const float*)d_in[9];
    const float* Wg_out = (const float*)d_in[10];
    const float* W      = (const float*)d_in[11];
    const float* bmlp   = (const float*)d_in[12];
    const float* Wf_g   = (const float*)d_in[13];
    const float* bf_g   = (const float*)d_in[14];
    const float* Wf_b   = (const float*)d_in[15];
    const float* Wf_bb  = (const float*)d_in[16];
    const float* W_out  = (const float*)d_in[17];
    const float* b_out  = (const float*)d_in[18];

    float *pff, *ph0, *pgA, *pgB, *pagg, *phA, *phB, *pfilm;
    cudaGetSymbolAddress((void**)&pff,  g_ff);
    cudaGetSymbolAddress((void**)&ph0,  g_h0);
    cudaGetSymbolAddress((void**)&pgA,  g_gA);
    cudaGetSymbolAddress((void**)&pgB,  g_gB);
    cudaGetSymbolAddress((void**)&pagg, g_agg);
    cudaGetSymbolAddress((void**)&phA,  g_hA);
    cudaGetSymbolAddress((void**)&phB,  g_hB);
    cudaGetSymbolAddress((void**)&pfilm, g_film);

    prep_kernel<<<NN / 256, 256>>>(x, Bf);
    knn_kernel<<<NN / 128, 128>>>();
    film_kernel<<<(DEPTHL * 2 * WID + 255) / 256, 256>>>(cond, Wf_g, bf_g, Wf_b, Wf_bb);

    // h0 = silu(ff @ W_in + b_in)
    gemm_ep<<<dim3(WID / BN, NN / BM), 256>>>(pff, W_in, nullptr, nullptr, b_in,
                                              nullptr, nullptr, nullptr, ph0,
                                              NN, FFD, WID, 1);
    // gfeat = silu(ff @ Wg_in + bg_in)
    gemm_ep<<<dim3(GW / BN, NN / BM), 256>>>(pff, Wg_in, nullptr, nullptr, bg_in,
                                             nullptr, nullptr, nullptr, pgA,
                                             NN, FFD, GW, 1);
    // graph message-passing layers
    float* cur = pgA; float* oth = pgB;
    for (int l = 0; l < GL; l++) {
        agg_kernel<<<NN, GW>>>(cur, pagg);
        gemm_ep<<<dim3(GW / BN, NN / BM), 256>>>(cur, Ws + (size_t)l * GW * GW,
                                                 pagg, Wn + (size_t)l * GW * GW,
                                                 bg + l * GW, nullptr, nullptr, nullptr,
                                                 oth, NN, GW, GW, 1);
        float* tmp = cur; cur = oth; oth = tmp;
    }
    // h = h0 + gfeat @ Wg_out   (no bias, no act, post-add h0)
    gemm_ep<<<dim3(WID / BN, NN / BM), 256>>>(cur, Wg_out, nullptr, nullptr, nullptr,
                                              nullptr, nullptr, ph0, phA,
                                              NN, GW, WID, 0);
    // FiLM trunk
    float* hc = phA; float* ho = phB;
    for (int l = 0; l < DEPTHL; l++) {
        const float* resid = (l == 2 || l == 5) ? ph0 : nullptr;
        gemm_ep<<<dim3(WID / BN, NN / BM), 256>>>(hc, W + (size_t)l * WID * WID,
                                                  nullptr, nullptr, bmlp + l * WID,
                                                  pfilm + l * 2 * WID,
                                                  pfilm + l * 2 * WID + WID,
                                                  resid, ho, NN, WID, WID, 1);
        float* tmp = hc; hc = ho; ho = tmp;
    }
    // out = (h @ W_out + b_out) * 0.01
    out_kernel<<<(NN * 32) / 256, 256>>>(hc, W_out, b_out, (float*)d_out);

    (void)in_sizes; (void)n_in; (void)out_size;
}

// round 3
// speedup vs baseline: 1.1860x; 1.1860x over previous
#include <cuda_runtime.h>
#include <math.h>

#define NN     65536
#define KNN    12
#define WID    256
#define GW     192
#define FFD    48
#define CONDD  64
#define DEPTHL 7
#define GL     4

// ---------------- scratch ----------------
__device__ float4 g_pts4[NN];
__device__ int    g_knn[NN * KNN];
__device__ float  g_ff[NN * FFD];
__device__ float  g_h0[NN * WID];
__device__ float  g_gA[NN * GW];
__device__ float  g_gB[NN * GW];
__device__ float  g_agg[NN * GW];
__device__ float  g_hA[NN * WID];
__device__ float  g_hB[NN * WID];
__device__ float  g_film[DEPTHL * 2 * WID];

// ---------------- prep: pts4 + fourier features ----------------
__global__ void prep_kernel(const float* __restrict__ x, const float* __restrict__ Bf) {
    __shared__ float Bs[72];
    if (threadIdx.x < 72) Bs[threadIdx.x] = Bf[threadIdx.x];
    __syncthreads();
    int n = blockIdx.x * blockDim.x + threadIdx.x;
    if (n >= NN) return;
    float x0 = x[n * 3 + 0], x1 = x[n * 3 + 1], x2 = x[n * 3 + 2];
    g_pts4[n] = make_float4(x0, x1, x2, x0 * x0 + x1 * x1 + x2 * x2);
#pragma unroll
    for (int sm = 0; sm < 24; sm++) {
        int s = sm >> 3, m = sm & 7;
        float p = x0 * Bs[s * 24 + 0 * 8 + m]
                + x1 * Bs[s * 24 + 1 * 8 + m]
                + x2 * Bs[s * 24 + 2 * 8 + m];
        g_ff[n * FFD + sm]      = sinf(p);
        g_ff[n * FFD + 24 + sm] = cosf(p);
    }
}

// ---------------- exact kNN ----------------
#define KTILE 1024
__global__ void knn_kernel() {
    __shared__ float4 sm[KTILE];
    int q = blockIdx.x * blockDim.x + threadIdx.x;
    float4 me = g_pts4[q];
    float m2x = -2.f * me.x, m2y = -2.f * me.y, m2z = -2.f * me.z;
    float dist[KNN];
    int   nidx[KNN];
#pragma unroll
    for (int i = 0; i < KNN; i++) { dist[i] = 3.0e38f; nidx[i] = 0; }

    for (int base = 0; base < NN; base += KTILE) {
        __syncthreads();
#pragma unroll
        for (int i = 0; i < KTILE / 256; i++)
            sm[threadIdx.x + 256 * i] = g_pts4[base + threadIdx.x + 256 * i];
        __syncthreads();
#pragma unroll 2
        for (int j = 0; j < KTILE; j += 4) {
            float d[4];
#pragma unroll
            for (int u = 0; u < 4; u++) {
                float4 c = sm[j + u];
                float dd = c.w + me.w;
                dd = fmaf(m2x, c.x, dd);
                dd = fmaf(m2y, c.y, dd);
                dd = fmaf(m2z, c.z, dd);
                d[u] = dd;
            }
            float mn = fminf(fminf(d[0], d[1]), fminf(d[2], d[3]));
            if (mn < dist[KNN - 1]) {
#pragma unroll
                for (int u = 0; u < 4; u++) {
                    int cj = base + j + u;
                    if (d[u] < dist[KNN - 1] && cj != q) {
                        dist[KNN - 1] = d[u]; nidx[KNN - 1] = cj;
#pragma unroll
                        for (int s = KNN - 1; s > 0; --s) {
                            if (dist[s] < dist[s - 1]) {   // strict < keeps lower-index first
                                float td = dist[s]; dist[s] = dist[s - 1]; dist[s - 1] = td;
                                int   ti = nidx[s]; nidx[s] = nidx[s - 1]; nidx[s - 1] = ti;
                            }
                        }
                    }
                }
            }
        }
    }
#pragma unroll
    for (int i = 0; i < KNN; i++) g_knn[q * KNN + i] = nidx[i];
}

// ---------------- FiLM params ----------------
__global__ void film_kernel(const float* __restrict__ cond,
                            const float* __restrict__ Wf_g, const float* __restrict__ bf_g,
                            const float* __restrict__ Wf_b, const float* __restrict__ bf_b) {
    __shared__ float cs[CONDD];
    if (threadIdx.x < CONDD) cs[threadIdx.x] = cond[threadIdx.x];
    __syncthreads();
    int t = blockIdx.x * blockDim.x + threadIdx.x;
    if (t >= DEPTHL * 2 * WID) return;
    int l = t / (2 * WID);
    int r = t % (2 * WID);
    int isb = r >> 8;
    int n = r & (WID - 1);
    const float* Wt = isb ? Wf_b : Wf_g;
    const float* bt = isb ? bf_b : bf_g;
    float s = bt[l * WID + n];
#pragma unroll 8
    for (int d = 0; d < CONDD; d++) s += cs[d] * Wt[(l * CONDD + d) * WID + n];
    g_film[l * 2 * WID + isb * WID + n] = s;
}

// ---------------- gather-mean over 12 neighbors ----------------
__global__ void agg_kernel(const float* __restrict__ gfeat, float* __restrict__ agg) {
    int n = blockIdx.x;
    int f = threadIdx.x;
    __shared__ int idx[KNN];
    if (f < KNN) idx[f] = g_knn[n * KNN + f];
    __syncthreads();
    float s = 0.f;
#pragma unroll
    for (int k = 0; k < KNN; k++) s += gfeat[idx[k] * GW + f];
    agg[n * GW + f] = s * (1.f / (float)KNN);
}

// ---------------- tiled GEMM, double-buffered, fused epilogue ----------------
// C = ep( A@Wt [+ A2@W2] + bias ), ep: optional FiLM, optional SiLU, optional residual.
#define BM 128
#define BK 16

template<int BN>
__global__ void __launch_bounds__(256, 2)
gemm_ep(const float* __restrict__ A,  const float* __restrict__ Wt,
        const float* __restrict__ A2, const float* __restrict__ W2,
        const float* __restrict__ bias,
        const float* __restrict__ gamma, const float* __restrict__ beta,
        const float* __restrict__ res,
        float* __restrict__ C,
        int Kd, int Nd, int doSilu) {
    constexpr int TN = BN / 16;         // 4 or 8 cols per thread
    constexpr int NB4 = BN / 64;        // float4 B loads per thread (1 or 2)
    __shared__ float As[2][BK][BM + 4];
    __shared__ float Bs[2][BK][BN];
    const int t = threadIdx.x;
    const int bm = blockIdx.y * BM, bn = blockIdx.x * BN;
    const int tx = t & 15, ty = t >> 4;
    const int ar = t >> 2;              // A load row 0..63
    const int ac = (t & 3) * 4;         // A load k-col

    const int nk1 = Kd / BK;
    const int nkT = (A2 != nullptr) ? 2 * nk1 : nk1;

    float acc[8][TN];
#pragma unroll
    for (int i = 0; i < 8; i++)
#pragma unroll
        for (int j = 0; j < TN; j++) acc[i][j] = 0.f;

    float4 va0, va1, vb[NB4];

    auto loadG = [&](int kt) {
        const float* Ap; const float* Wp; int k0;
        if (kt < nk1) { Ap = A; Wp = Wt; k0 = kt * BK; }
        else          { Ap = A2; Wp = W2; k0 = (kt - nk1) * BK; }
        va0 = *reinterpret_cast<const float4*>(&Ap[(size_t)(bm + ar) * Kd + k0 + ac]);
        va1 = *reinterpret_cast<const float4*>(&Ap[(size_t)(bm + ar + 64) * Kd + k0 + ac]);
        if (BN == 64) {
            vb[0] = *reinterpret_cast<const float4*>(&Wp[(size_t)(k0 + (t >> 4)) * Nd + bn + (t & 15) * 4]);
        } else {
#pragma unroll
            for (int u = 0; u < NB4; u++)
                vb[u] = *reinterpret_cast<const float4*>(&Wp[(size_t)(k0 + (t >> 5) + 8 * u) * Nd + bn + (t & 31) * 4]);
        }
    };
    auto storeS = [&](int buf) {
        As[buf][ac + 0][ar] = va0.x; As[buf][ac + 1][ar] = va0.y;
        As[buf][ac + 2][ar] = va0.z; As[buf][ac + 3][ar] = va0.w;
        As[buf][ac + 0][ar + 64] = va1.x; As[buf][ac + 1][ar + 64] = va1.y;
        As[buf][ac + 2][ar + 64] = va1.z; As[buf][ac + 3][ar + 64] = va1.w;
        if (BN == 64) {
            *reinterpret_cast<float4*>(&Bs[buf][t >> 4][(t & 15) * 4]) = vb[0];
        } else {
#pragma unroll
            for (int u = 0; u < NB4; u++)
                *reinterpret_cast<float4*>(&Bs[buf][(t >> 5) + 8 * u][(t & 31) * 4]) = vb[u];
        }
    };

    loadG(0);
    storeS(0);
    __syncthreads();
    int buf = 0;
    for (int kt = 0; kt < nkT; kt++) {
        bool more = (kt + 1 < nkT);
        if (more) loadG(kt + 1);
#pragma unroll
        for (int kk = 0; kk < BK; kk++) {
            float4 a0 = *reinterpret_cast<const float4*>(&As[buf][kk][ty * 8]);
            float4 a1 = *reinterpret_cast<const float4*>(&As[buf][kk][ty * 8 + 4]);
            float af[8] = {a0.x, a0.y, a0.z, a0.w, a1.x, a1.y, a1.z, a1.w};
            float bf[TN];
#pragma unroll
            for (int j0 = 0; j0 < TN; j0 += 4) {
                float4 bb = *reinterpret_cast<const float4*>(&Bs[buf][kk][tx * TN + j0]);
                bf[j0] = bb.x; bf[j0 + 1] = bb.y; bf[j0 + 2] = bb.z; bf[j0 + 3] = bb.w;
            }
#pragma unroll
            for (int i = 0; i < 8; i++)
#pragma unroll
                for (int j = 0; j < TN; j++)
                    acc[i][j] = fmaf(af[i], bf[j], acc[i][j]);
        }
        if (more) {
            storeS(buf ^ 1);
            __syncthreads();
            buf ^= 1;
        }
    }

#pragma unroll
    for (int i = 0; i < 8; i++) {
        int m = bm + ty * 8 + i;
        size_t rowoff = (size_t)m * Nd + bn + tx * TN;
#pragma unroll
        for (int j0 = 0; j0 < TN; j0 += 4) {
            int n0 = bn + tx * TN + j0;
            float v[4] = {acc[i][j0], acc[i][j0 + 1], acc[i][j0 + 2], acc[i][j0 + 3]};
            if (bias) {
                float4 bb = *reinterpret_cast<const float4*>(&bias[n0]);
                v[0] += bb.x; v[1] += bb.y; v[2] += bb.z; v[3] += bb.w;
            }
            if (gamma) {
                float4 gg = *reinterpret_cast<const float4*>(&gamma[n0]);
                float4 be = *reinterpret_cast<const float4*>(&beta[n0]);
                v[0] = v[0] * (1.f + gg.x) + be.x;
                v[1] = v[1] * (1.f + gg.y) + be.y;
                v[2] = v[2] * (1.f + gg.z) + be.z;
                v[3] = v[3] * (1.f + gg.w) + be.w;
            }
            if (doSilu) {
#pragma unroll
                for (int u = 0; u < 4; u++) v[u] = v[u] / (1.f + expf(-v[u]));
            }
            if (res) {
                float4 rr = *reinterpret_cast<const float4*>(&res[rowoff + j0]);
                v[0] += rr.x; v[1] += rr.y; v[2] += rr.z; v[3] += rr.w;
            }
            float4 o; o.x = v[0]; o.y = v[1]; o.z = v[2]; o.w = v[3];
            *reinterpret_cast<float4*>(&C[rowoff + j0]) = o;
        }
    }
}

// ---------------- final projection ----------------
__global__ void out_kernel(const float* __restrict__ h,
                           const float* __restrict__ Wout, const float* __restrict__ bout,
                           float* __restrict__ out) {
    int gt = blockIdx.x * blockDim.x + threadIdx.x;
    int n = gt >> 5;
    int lane = gt & 31;
    if (n >= NN) return;
    float a0 = 0.f, a1 = 0.f, a2 = 0.f;
#pragma unroll
    for (int k = lane; k < WID; k += 32) {
        float hv = h[(size_t)n * WID + k];
        a0 = fmaf(hv, Wout[k * 3 + 0], a0);
        a1 = fmaf(hv, Wout[k * 3 + 1], a1);
        a2 = fmaf(hv, Wout[k * 3 + 2], a2);
    }
#pragma unroll
    for (int off = 16; off > 0; off >>= 1) {
        a0 += __shfl_down_sync(0xffffffffu, a0, off);
        a1 += __shfl_down_sync(0xffffffffu, a1, off);
        a2 += __shfl_down_sync(0xffffffffu, a2, off);
    }
    if (lane == 0) {
        out[n * 3 + 0] = (a0 + bout[0]) * 0.01f;
        out[n * 3 + 1] = (a1 + bout[1]) * 0.01f;
        out[n * 3 + 2] = (a2 + bout[2]) * 0.01f;
    }
}

// ---------------- host launcher ----------------
extern "C" void kernel_launch(void* const* d_in, const int* in_sizes, int n_in,
                              void* d_out, int out_size) {
    const float* x      = (const float*)d_in[0];
    const float* cond   = (const float*)d_in[1];
    const float* Bf     = (const float*)d_in[2];
    const float* W_in   = (const float*)d_in[3];
    const float* b_in   = (const float*)d_in[4];
    const float* Wg_in  = (const float*)d_in[5];
    const float* bg_in  = (const float*)d_in[6];
    const float* Ws     = (const float*)d_in[7];
    const float* Wn     = (const float*)d_in[8];
    const float* bg     = (const float*)d_in[9];
    const float* Wg_out = (const float*)d_in[10];
    const float* W      = (const float*)d_in[11];
    const float* bmlp   = (const float*)d_in[12];
    const float* Wf_g   = (const float*)d_in[13];
    const float* bf_g   = (const float*)d_in[14];
    const float* Wf_b   = (const float*)d_in[15];
    const float* bf_bb  = (const float*)d_in[16];
    const float* W_out  = (const float*)d_in[17];
    const float* b_out  = (const float*)d_in[18];

    float *pff, *ph0, *pgA, *pgB, *pagg, *phA, *phB, *pfilm;
    cudaGetSymbolAddress((void**)&pff,  g_ff);
    cudaGetSymbolAddress((void**)&ph0,  g_h0);
    cudaGetSymbolAddress((void**)&pgA,  g_gA);
    cudaGetSymbolAddress((void**)&pgB,  g_gB);
    cudaGetSymbolAddress((void**)&pagg, g_agg);
    cudaGetSymbolAddress((void**)&phA,  g_hA);
    cudaGetSymbolAddress((void**)&phB,  g_hB);
    cudaGetSymbolAddress((void**)&pfilm, g_film);

    prep_kernel<<<NN / 256, 256>>>(x, Bf);
    knn_kernel<<<NN / 256, 256>>>();
    film_kernel<<<(DEPTHL * 2 * WID + 255) / 256, 256>>>(cond, Wf_g, bf_g, Wf_b, bf_bb);

    dim3 gridW(WID / 128, NN / BM);     // N=256 GEMMs
    dim3 gridG(GW / 64,  NN / BM);      // N=192 GEMMs

    // h0 = silu(ff @ W_in + b_in)
    gemm_ep<128><<<gridW, 256>>>(pff, W_in, nullptr, nullptr, b_in,
                                 nullptr, nullptr, nullptr, ph0, FFD, WID, 1);
    // gfeat = silu(ff @ Wg_in + bg_in)
    gemm_ep<64><<<gridG, 256>>>(pff, Wg_in, nullptr, nullptr, bg_in,
                                nullptr, nullptr, nullptr, pgA, FFD, GW, 1);
    // graph message-passing layers
    float* cur = pgA; float* oth = pgB;
    for (int l = 0; l < GL; l++) {
        agg_kernel<<<NN, GW>>>(cur, pagg);
        gemm_ep<64><<<gridG, 256>>>(cur, Ws + (size_t)l * GW * GW,
                                    pagg, Wn + (size_t)l * GW * GW,
                                    bg + l * GW, nullptr, nullptr, nullptr,
                                    oth, GW, GW, 1);
        float* tmp = cur; cur = oth; oth = tmp;
    }
    // h = h0 + gfeat @ Wg_out
    gemm_ep<128><<<gridW, 256>>>(cur, Wg_out, nullptr, nullptr, nullptr,
                                 nullptr, nullptr, ph0, phA, GW, WID, 0);
    // FiLM trunk
    float* hc = phA; float* ho = phB;
    for (int l = 0; l < DEPTHL; l++) {
        const float* resid = (l == 2 || l == 5) ? ph0 : nullptr;
        gemm_ep<128><<<gridW, 256>>>(hc, W + (size_t)l * WID * WID,
                                     nullptr, nullptr, bmlp + l * WID,
                                     pfilm + l * 2 * WID,
                                     pfilm + l * 2 * WID + WID,
                                     resid, ho, WID, WID, 1);
        float* tmp = hc; hc = ho; ho = tmp;
    }
    out_kernel<<<(NN * 32) / 256, 256>>>(hc, W_out, b_out, (float*)d_out);

    (void)in_sizes; (void)n_in; (void)out_size;
}

// round 6
// speedup vs baseline: 1.6308x; 1.3751x over previous
#include <cuda_runtime.h>
#include <cuda_bf16.h>
#include <math.h>
#include <stdint.h>

#define NN     65536
#define KNN    12
#define WID    256
#define GW     192
#define FFD    48
#define FFP    64      // padded FF K
#define CONDD  64
#define DEPTHL 7
#define GL     4

// ---------------- scratch ----------------
__device__ float4 g_pts4[NN];
__device__ int    g_knn[NN * KNN];
__device__ float  g_h0[NN * WID];
__device__ float  g_gA[NN * GW];
__device__ float  g_gB[NN * GW];
__device__ float  g_hA[NN * WID];
__device__ float  g_hB[NN * WID];
__device__ float  g_film[DEPTHL * 2 * WID];

__device__ __nv_bfloat16 g_ffH[NN * FFP];
__device__ __nv_bfloat16 g_ffL[NN * FFP];
__device__ __nv_bfloat16 g_gAH[NN * GW];
__device__ __nv_bfloat16 g_gAL[NN * GW];
__device__ __nv_bfloat16 g_gBH[NN * GW];
__device__ __nv_bfloat16 g_gBL[NN * GW];
__device__ __nv_bfloat16 g_aggH[NN * GW];
__device__ __nv_bfloat16 g_aggL[NN * GW];
__device__ __nv_bfloat16 g_hAH[NN * WID];
__device__ __nv_bfloat16 g_hAL[NN * WID];
__device__ __nv_bfloat16 g_hBH[NN * WID];
__device__ __nv_bfloat16 g_hBL[NN * WID];

// transposed/split weights, stored [N rows][K cols] bf16
__device__ __nv_bfloat16 g_WinT_H[WID * FFP],  g_WinT_L[WID * FFP];
__device__ __nv_bfloat16 g_WginT_H[GW * FFP],  g_WginT_L[GW * FFP];
__device__ __nv_bfloat16 g_WsT_H[GL * GW * GW],  g_WsT_L[GL * GW * GW];
__device__ __nv_bfloat16 g_WnT_H[GL * GW * GW],  g_WnT_L[GL * GW * GW];
__device__ __nv_bfloat16 g_WgoT_H[WID * GW],   g_WgoT_L[WID * GW];
__device__ __nv_bfloat16 g_WT_H[DEPTHL * WID * WID], g_WT_L[DEPTHL * WID * WID];

// ---------------- PTX helpers (portable ISA only: cp.async / ldmatrix / mma.sync) ----------------
__device__ __forceinline__ uint32_t smem_u32(const void* p) {
    uint32_t a;
    asm("{ .reg .u64 t; cvta.to.shared.u64 t, %1; cvt.u32.u64 %0, t; }" : "=r"(a) : "l"(p));
    return a;
}
__device__ __forceinline__ void cp16(uint32_t s, const void* g) {
    asm volatile("cp.async.cg.shared.global [%0], [%1], 16;" :: "r"(s), "l"(g));
}
__device__ __forceinline__ void ldsm4(uint32_t* r, uint32_t a) {
    asm volatile("ldmatrix.sync.aligned.m8n8.x4.shared.b16 {%0,%1,%2,%3}, [%4];"
                 : "=r"(r[0]), "=r"(r[1]), "=r"(r[2]), "=r"(r[3]) : "r"(a));
}
__device__ __forceinline__ void mma16816(float* d, const uint32_t* a, uint32_t b0, uint32_t b1) {
    asm volatile("mma.sync.aligned.m16n8k16.row.col.f32.bf16.bf16.f32 "
                 "{%0,%1,%2,%3}, {%4,%5,%6,%7}, {%8,%9}, {%0,%1,%2,%3};"
                 : "+f"(d[0]), "+f"(d[1]), "+f"(d[2]), "+f"(d[3])
                 : "r"(a[0]), "r"(a[1]), "r"(a[2]), "r"(a[3]), "r"(b0), "r"(b1));
}

// ---------------- prep: pts4 + bf16-split fourier features (K padded to 64) ----------------
__global__ void prep_kernel(const float* __restrict__ x, const float* __restrict__ Bf) {
    __shared__ float Bs[72];
    if (threadIdx.x < 72) Bs[threadIdx.x] = Bf[threadIdx.x];
    __syncthreads();
    int n = blockIdx.x * blockDim.x + threadIdx.x;
    if (n >= NN) return;
    float x0 = x[n * 3 + 0], x1 = x[n * 3 + 1], x2 = x[n * 3 + 2];
    g_pts4[n] = make_float4(x0, x1, x2, x0 * x0 + x1 * x1 + x2 * x2);
    float f[FFD];
#pragma unroll
    for (int sm = 0; sm < 24; sm++) {
        int s = sm >> 3, m = sm & 7;
        float p = x0 * Bs[s * 24 + 0 * 8 + m]
                + x1 * Bs[s * 24 + 1 * 8 + m]
                + x2 * Bs[s * 24 + 2 * 8 + m];
        f[sm] = sinf(p); f[24 + sm] = cosf(p);
    }
#pragma unroll
    for (int k = 0; k < FFP; k++) {
        float v = (k < FFD) ? f[k] : 0.f;
        __nv_bfloat16 h = __float2bfloat16(v);
        g_ffH[n * FFP + k] = h;
        g_ffL[n * FFP + k] = __float2bfloat16(v - __bfloat162float(h));
    }
}

// ---------------- exact kNN ----------------
#define KTILE 1024
__global__ void knn_kernel() {
    __shared__ float4 sm[KTILE];
    int q = blockIdx.x * blockDim.x + threadIdx.x;
    float4 me = g_pts4[q];
    float m2x = -2.f * me.x, m2y = -2.f * me.y, m2z = -2.f * me.z;
    float dist[KNN];
    int   nidx[KNN];
#pragma unroll
    for (int i = 0; i < KNN; i++) { dist[i] = 3.0e38f; nidx[i] = 0; }

    for (int base = 0; base < NN; base += KTILE) {
        __syncthreads();
#pragma unroll
        for (int i = 0; i < KTILE / 256; i++)
            sm[threadIdx.x + 256 * i] = g_pts4[base + threadIdx.x + 256 * i];
        __syncthreads();
#pragma unroll 2
        for (int j = 0; j < KTILE; j += 4) {
            float d[4];
#pragma unroll
            for (int u = 0; u < 4; u++) {
                float4 c = sm[j + u];
                float dd = c.w + me.w;
                dd = fmaf(m2x, c.x, dd);
                dd = fmaf(m2y, c.y, dd);
                dd = fmaf(m2z, c.z, dd);
                d[u] = dd;
            }
            float mn = fminf(fminf(d[0], d[1]), fminf(d[2], d[3]));
            if (mn < dist[KNN - 1]) {
#pragma unroll
                for (int u = 0; u < 4; u++) {
                    int cj = base + j + u;
                    if (d[u] < dist[KNN - 1] && cj != q) {
                        dist[KNN - 1] = d[u]; nidx[KNN - 1] = cj;
#pragma unroll
                        for (int s = KNN - 1; s > 0; --s) {
                            if (dist[s] < dist[s - 1]) {
                                float td = dist[s]; dist[s] = dist[s - 1]; dist[s - 1] = td;
                                int   ti = nidx[s]; nidx[s] = nidx[s - 1]; nidx[s - 1] = ti;
                            }
                        }
                    }
                }
            }
        }
    }
#pragma unroll
    for (int i = 0; i < KNN; i++) g_knn[q * KNN + i] = nidx[i];
}

// ---------------- FiLM params ----------------
__global__ void film_kernel(const float* __restrict__ cond,
                            const float* __restrict__ Wf_g, const float* __restrict__ bf_g,
                            const float* __restrict__ Wf_b, const float* __restrict__ bf_b) {
    __shared__ float cs[CONDD];
    if (threadIdx.x < CONDD) cs[threadIdx.x] = cond[threadIdx.x];
    __syncthreads();
    int t = blockIdx.x * blockDim.x + threadIdx.x;
    if (t >= DEPTHL * 2 * WID) return;
    int l = t / (2 * WID);
    int r = t % (2 * WID);
    int isb = r >> 8;
    int n = r & (WID - 1);
    const float* Wt = isb ? Wf_b : Wf_g;
    const float* bt = isb ? bf_b : bf_g;
    float s = bt[l * WID + n];
#pragma unroll 8
    for (int d = 0; d < CONDD; d++) s += cs[d] * Wt[(l * CONDD + d) * WID + n];
    g_film[l * 2 * WID + isb * WID + n] = s;
}

// ---------------- weight transpose + bf16 split:  dst[n][k] = src[k][n] ----------------
__global__ void wconv(const float* __restrict__ src, __nv_bfloat16* __restrict__ dH,
                      __nv_bfloat16* __restrict__ dL, int K, int N, int Kp, int total) {
    int t = blockIdx.x * blockDim.x + threadIdx.x;
    if (t >= total) return;
    int k = t % Kp;
    int rn_ = t / Kp;
    int n = rn_ % N;
    int l = rn_ / N;
    float v = (k < K) ? src[((size_t)l * K + k) * N + n] : 0.f;
    __nv_bfloat16 h = __float2bfloat16(v);
    dH[t] = h;
    dL[t] = __float2bfloat16(v - __bfloat162float(h));
}

// ---------------- gather-mean, bf16-split output ----------------
__global__ void agg_kernel(const float* __restrict__ gfeat,
                           __nv_bfloat16* __restrict__ aggH, __nv_bfloat16* __restrict__ aggL) {
    int n = blockIdx.x;
    int f = threadIdx.x;
    __shared__ int idx[KNN];
    if (f < KNN) idx[f] = g_knn[n * KNN + f];
    __syncthreads();
    float s = 0.f;
#pragma unroll
    for (int k = 0; k < KNN; k++) s += gfeat[(size_t)idx[k] * GW + f];
    s *= (1.f / (float)KNN);
    __nv_bfloat16 h = __float2bfloat16(s);
    aggH[(size_t)n * GW + f] = h;
    aggL[(size_t)n * GW + f] = __float2bfloat16(s - __bfloat162float(h));
}

// ---------------- warp-MMA bf16-split GEMM (fallback HMMA), fused epilogue ----------------
// C = ep( A0@B0^T [+ A1@B1^T] + bias ); A/B given as bf16 hi/lo pairs (3-pass split).
// Tile 128x64, BK=32, 8 warps (4m x 2n), double-buffered cp.async.
__global__ void __launch_bounds__(256, 2)
hgemm(const __nv_bfloat16* __restrict__ AH0, const __nv_bfloat16* __restrict__ AL0,
      const __nv_bfloat16* __restrict__ BH0, const __nv_bfloat16* __restrict__ BL0, int K0,
      const __nv_bfloat16* __restrict__ AH1, const __nv_bfloat16* __restrict__ AL1,
      const __nv_bfloat16* __restrict__ BH1, const __nv_bfloat16* __restrict__ BL1, int K1,
      const float* __restrict__ bias, const float* __restrict__ gamma,
      const float* __restrict__ beta, const float* __restrict__ res, int doSilu,
      float* __restrict__ Cf, __nv_bfloat16* __restrict__ CH, __nv_bfloat16* __restrict__ CL,
      int Nd)
{
    __shared__ __align__(16) __nv_bfloat16 sA[2][2][128 * 32];  // [buf][hi/lo]
    __shared__ __align__(16) __nv_bfloat16 sB[2][2][64 * 32];
    const int t = threadIdx.x, lane = t & 31, wid = t >> 5;
    const int bm = blockIdx.y * 128, bn = blockIdx.x * 64;
    const int wm = (wid & 3) * 32, wn = (wid >> 2) * 32;

    float acc[2][4][4];
#pragma unroll
    for (int i = 0; i < 2; i++)
#pragma unroll
        for (int j = 0; j < 4; j++)
#pragma unroll
            for (int q = 0; q < 4; q++) acc[i][j][q] = 0.f;

    const int nch0 = K0 >> 5;
    const int nch = nch0 + (K1 >> 5);

    auto issue = [&](int c, int b) {
        const __nv_bfloat16 *aH, *aL, *bH, *bL; int Ks, k0;
        if (c < nch0) { aH = AH0; aL = AL0; bH = BH0; bL = BL0; Ks = K0; k0 = c * 32; }
        else          { aH = AH1; aL = AL1; bH = BH1; bL = BL1; Ks = K1; k0 = (c - nch0) * 32; }
#pragma unroll
        for (int i = 0; i < 2; i++) {                 // A: 128 rows x 4 chunks of 16B
            int id = t + 256 * i;
            int r = id >> 2, cc = id & 3;
            uint32_t soff = (uint32_t)r * 64u + (uint32_t)((cc ^ ((r >> 1) & 3)) * 16);
            size_t go = (size_t)(bm + r) * Ks + k0 + cc * 8;
            cp16(smem_u32(&sA[b][0][0]) + soff, aH + go);
            cp16(smem_u32(&sA[b][1][0]) + soff, aL + go);
        }
        {                                              // B: 64 rows x 4 chunks
            int r = t >> 2, cc = t & 3;
            uint32_t soff = (uint32_t)r * 64u + (uint32_t)((cc ^ ((r >> 1) & 3)) * 16);
            size_t go = (size_t)(bn + r) * Ks + k0 + cc * 8;
            cp16(smem_u32(&sB[b][0][0]) + soff, bH + go);
            cp16(smem_u32(&sB[b][1][0]) + soff, bL + go);
        }
        asm volatile("cp.async.commit_group;" ::: "memory");
    };

    issue(0, 0);
    int buf = 0;
    for (int c = 0; c < nch; c++) {
        if (c + 1 < nch) {
            issue(c + 1, buf ^ 1);
            asm volatile("cp.async.wait_group 1;" ::: "memory");
        } else {
            asm volatile("cp.async.wait_group 0;" ::: "memory");
        }
        __syncthreads();
#pragma unroll
        for (int kstep = 0; kstep < 2; kstep++) {
            uint32_t ah[2][4], al[2][4], bh[2][4], bl[2][4];
#pragma unroll
            for (int mt = 0; mt < 2; mt++) {
                int r = wm + mt * 16 + (lane & 15);
                int kc = kstep * 2 + (lane >> 4);
                uint32_t soff = (uint32_t)r * 64u + (uint32_t)((kc ^ ((r >> 1) & 3)) * 16);
                ldsm4(ah[mt], smem_u32(&sA[buf][0][0]) + soff);
                ldsm4(al[mt], smem_u32(&sA[buf][1][0]) + soff);
            }
#pragma unroll
            for (int p = 0; p < 2; p++) {
                int r = wn + p * 16 + (lane & 15);
                int kc = kstep * 2 + (lane >> 4);
                uint32_t soff = (uint32_t)r * 64u + (uint32_t)((kc ^ ((r >> 1) & 3)) * 16);
                ldsm4(bh[p], smem_u32(&sB[buf][0][0]) + soff);
                ldsm4(bl[p], smem_u32(&sB[buf][1][0]) + soff);
            }
#pragma unroll
            for (int mt = 0; mt < 2; mt++)
#pragma unroll
                for (int nt = 0; nt < 4; nt++) {
                    int p = nt >> 1, s = nt & 1;
                    mma16816(acc[mt][nt], ah[mt], bh[p][s], bh[p][s + 2]);  // Ah*Bh
                    mma16816(acc[mt][nt], ah[mt], bl[p][s], bl[p][s + 2]);  // Ah*Bl
                    mma16816(acc[mt][nt], al[mt], bh[p][s], bh[p][s + 2]);  // Al*Bh
                }
        }
        __syncthreads();
        buf ^= 1;
    }

    // fused epilogue
#pragma unroll
    for (int mt = 0; mt < 2; mt++)
#pragma unroll
        for (int nt = 0; nt < 4; nt++) {
            int gn = bn + wn + nt * 8 + (lane & 3) * 2;
            float2 bi = make_float2(0.f, 0.f);
            float2 gg = make_float2(0.f, 0.f), be = make_float2(0.f, 0.f);
            if (bias) bi = *reinterpret_cast<const float2*>(&bias[gn]);
            if (gamma) {
                gg = *reinterpret_cast<const float2*>(&gamma[gn]);
                be = *reinterpret_cast<const float2*>(&beta[gn]);
            }
#pragma unroll
            for (int hh = 0; hh < 2; hh++) {
                int gm = bm + wm + mt * 16 + (lane >> 2) + hh * 8;
                float v0 = acc[mt][nt][2 * hh + 0];
                float v1 = acc[mt][nt][2 * hh + 1];
                if (bias)  { v0 += bi.x; v1 += bi.y; }
                if (gamma) { v0 = v0 * (1.f + gg.x) + be.x; v1 = v1 * (1.f + gg.y) + be.y; }
                if (doSilu) {
                    v0 = v0 / (1.f + expf(-v0));
                    v1 = v1 / (1.f + expf(-v1));
                }
                size_t go = (size_t)gm * Nd + gn;
                if (res) {
                    float2 rr = *reinterpret_cast<const float2*>(&res[go]);
                    v0 += rr.x; v1 += rr.y;
                }
                *reinterpret_cast<float2*>(&Cf[go]) = make_float2(v0, v1);
                if (CH) {
                    __nv_bfloat16 h0b = __float2bfloat16(v0);
                    __nv_bfloat16 h1b = __float2bfloat16(v1);
                    __nv_bfloat162 hp; hp.x = h0b; hp.y = h1b;
                    *reinterpret_cast<__nv_bfloat162*>(&CH[go]) = hp;
                    __nv_bfloat162 lp;
                    lp.x = __float2bfloat16(v0 - __bfloat162float(h0b));
                    lp.y = __float2bfloat16(v1 - __bfloat162float(h1b));
                    *reinterpret_cast<__nv_bfloat162*>(&CL[go]) = lp;
                }
            }
        }
}

// ---------------- final projection ----------------
__global__ void out_kernel(const float* __restrict__ h,
                           const float* __restrict__ Wout, const float* __restrict__ bout,
                           float* __restrict__ out) {
    int gt = blockIdx.x * blockDim.x + threadIdx.x;
    int n = gt >> 5;
    int lane = gt & 31;
    if (n >= NN) return;
    float a0 = 0.f, a1 = 0.f, a2 = 0.f;
#pragma unroll
    for (int k = lane; k < WID; k += 32) {
        float hv = h[(size_t)n * WID + k];
        a0 = fmaf(hv, Wout[k * 3 + 0], a0);
        a1 = fmaf(hv, Wout[k * 3 + 1], a1);
        a2 = fmaf(hv, Wout[k * 3 + 2], a2);
    }
#pragma unroll
    for (int off = 16; off > 0; off >>= 1) {
        a0 += __shfl_down_sync(0xffffffffu, a0, off);
        a1 += __shfl_down_sync(0xffffffffu, a1, off);
        a2 += __shfl_down_sync(0xffffffffu, a2, off);
    }
    if (lane == 0) {
        out[n * 3 + 0] = (a0 + bout[0]) * 0.01f;
        out[n * 3 + 1] = (a1 + bout[1]) * 0.01f;
        out[n * 3 + 2] = (a2 + bout[2]) * 0.01f;
    }
}

// ---------------- host launcher ----------------
extern "C" void kernel_launch(void* const* d_in, const int* in_sizes, int n_in,
                              void* d_out, int out_size) {
    const float* x      = (const float*)d_in[0];
    const float* cond   = (const float*)d_in[1];
    const float* Bf     = (const float*)d_in[2];
    const float* W_in   = (const float*)d_in[3];
    const float* b_in   = (const float*)d_in[4];
    const float* Wg_in  = (const float*)d_in[5];
    const float* bg_in  = (const float*)d_in[6];
    const float* Ws     = (const float*)d_in[7];
    const float* Wn     = (const float*)d_in[8];
    const float* bg     = (const float*)d_in[9];
    const float* Wg_out = (const float*)d_in[10];
    const float* W      = (const float*)d_in[11];
    const float* bmlp   = (const float*)d_in[12];
    const float* Wf_g   = (const float*)d_in[13];
    const float* bf_g   = (const float*)d_in[14];
    const float* Wf_b   = (const float*)d_in[15];
    const float* bf_bb  = (const float*)d_in[16];
    const float* W_out  = (const float*)d_in[17];
    const float* b_out  = (const float*)d_in[18];

    float *ph0, *pgA, *pgB, *phA, *phB, *pfilm;
    cudaGetSymbolAddress((void**)&ph0,  g_h0);
    cudaGetSymbolAddress((void**)&pgA,  g_gA);
    cudaGetSymbolAddress((void**)&pgB,  g_gB);
    cudaGetSymbolAddress((void**)&phA,  g_hA);
    cudaGetSymbolAddress((void**)&phB,  g_hB);
    cudaGetSymbolAddress((void**)&pfilm, g_film);
    __nv_bfloat16 *pffH, *pffL, *pgAH, *pgAL, *pgBH, *pgBL, *paggH, *paggL;
    __nv_bfloat16 *phAH, *phAL, *phBH, *phBL;
    __nv_bfloat16 *pWinH, *pWinL, *pWginH, *pWginL, *pWsH, *pWsL, *pWnH, *pWnL;
    __nv_bfloat16 *pWgoH, *pWgoL, *pWH, *pWL;
    cudaGetSymbolAddress((void**)&pffH, g_ffH);   cudaGetSymbolAddress((void**)&pffL, g_ffL);
    cudaGetSymbolAddress((void**)&pgAH, g_gAH);   cudaGetSymbolAddress((void**)&pgAL, g_gAL);
    cudaGetSymbolAddress((void**)&pgBH, g_gBH);   cudaGetSymbolAddress((void**)&pgBL, g_gBL);
    cudaGetSymbolAddress((void**)&paggH, g_aggH); cudaGetSymbolAddress((void**)&paggL, g_aggL);
    cudaGetSymbolAddress((void**)&phAH, g_hAH);   cudaGetSymbolAddress((void**)&phAL, g_hAL);
    cudaGetSymbolAddress((void**)&phBH, g_hBH);   cudaGetSymbolAddress((void**)&phBL, g_hBL);
    cudaGetSymbolAddress((void**)&pWinH, g_WinT_H);  cudaGetSymbolAddress((void**)&pWinL, g_WinT_L);
    cudaGetSymbolAddress((void**)&pWginH, g_WginT_H); cudaGetSymbolAddress((void**)&pWginL, g_WginT_L);
    cudaGetSymbolAddress((void**)&pWsH, g_WsT_H);  cudaGetSymbolAddress((void**)&pWsL, g_WsT_L);
    cudaGetSymbolAddress((void**)&pWnH, g_WnT_H);  cudaGetSymbolAddress((void**)&pWnL, g_WnT_L);
    cudaGetSymbolAddress((void**)&pWgoH, g_WgoT_H); cudaGetSymbolAddress((void**)&pWgoL, g_WgoT_L);
    cudaGetSymbolAddress((void**)&pWH, g_WT_H);    cudaGetSymbolAddress((void**)&pWL, g_WT_L);

    prep_kernel<<<NN / 256, 256>>>(x, Bf);
    knn_kernel<<<NN / 256, 256>>>();
    film_kernel<<<(DEPTHL * 2 * WID + 255) / 256, 256>>>(cond, Wf_g, bf_g, Wf_b, bf_bb);

    // weight transposes + bf16 split
    {
        int tot;
        tot = WID * FFP;            wconv<<<(tot + 255) / 256, 256>>>(W_in,   pWinH,  pWinL,  FFD, WID, FFP, tot);
        tot = GW * FFP;             wconv<<<(tot + 255) / 256, 256>>>(Wg_in,  pWginH, pWginL, FFD, GW,  FFP, tot);
        tot = GL * GW * GW;         wconv<<<(tot + 255) / 256, 256>>>(Ws,     pWsH,   pWsL,   GW,  GW,  GW,  tot);
        tot = GL * GW * GW;         wconv<<<(tot + 255) / 256, 256>>>(Wn,     pWnH,   pWnL,   GW,  GW,  GW,  tot);
        tot = WID * GW;             wconv<<<(tot + 255) / 256, 256>>>(Wg_out, pWgoH,  pWgoL,  GW,  WID, GW,  tot);
        tot = DEPTHL * WID * WID;   wconv<<<(tot + 255) / 256, 256>>>(W,      pWH,    pWL,    WID, WID, WID, tot);
    }

    dim3 gridW(WID / 64, NN / 128);   // N=256
    dim3 gridG(GW / 64,  NN / 128);   // N=192

    // h0 = silu(ff @ W_in + b_in)   (fp32 only; h0 never feeds a GEMM A)
    hgemm<<<gridW, 256>>>(pffH, pffL, pWinH, pWinL, FFP,
                          nullptr, nullptr, nullptr, nullptr, 0,
                          b_in, nullptr, nullptr, nullptr, 1,
                          ph0, nullptr, nullptr, WID);
    // gfeat = silu(ff @ Wg_in + bg_in)
    hgemm<<<gridG, 256>>>(pffH, pffL, pWginH, pWginL, FFP,
                          nullptr, nullptr, nullptr, nullptr, 0,
                          bg_in, nullptr, nullptr, nullptr, 1,
                          pgA, pgAH, pgAL, GW);
    // graph message-passing
    float* cf = pgA;  __nv_bfloat16* cH = pgAH; __nv_bfloat16* cL = pgAL;
    float* of = pgB;  __nv_bfloat16* oH = pgBH; __nv_bfloat16* oL = pgBL;
    for (int l = 0; l < GL; l++) {
        agg_kernel<<<NN, GW>>>(cf, paggH, paggL);
        hgemm<<<gridG, 256>>>(cH, cL, pWsH + (size_t)l * GW * GW, pWsL + (size_t)l * GW * GW, GW,
                              paggH, paggL, pWnH + (size_t)l * GW * GW, pWnL + (size_t)l * GW * GW, GW,
                              bg + l * GW, nullptr, nullptr, nullptr, 1,
                              of, oH, oL, GW);
        float* tf = cf; cf = of; of = tf;
        __nv_bfloat16* th = cH; cH = oH; oH = th;
        __nv_bfloat16* tl = cL; cL = oL; oL = tl;
    }
    // h = h0 + gfeat @ Wg_out
    hgemm<<<gridW, 256>>>(cH, cL, pWgoH, pWgoL, GW,
                          nullptr, nullptr, nullptr, nullptr, 0,
                          nullptr, nullptr, nullptr, ph0, 0,
                          phA, phAH, phAL, WID);
    // FiLM trunk
    float* hf = phA;  __nv_bfloat16* hH = phAH; __nv_bfloat16* hL = phAL;
    float* gf = phB;  __nv_bfloat16* gH = phBH; __nv_bfloat16* gL = phBL;
    for (int l = 0; l < DEPTHL; l++) {
        const float* resid = (l == 2 || l == 5) ? ph0 : nullptr;
        bool last = (l == DEPTHL - 1);
        hgemm<<<gridW, 256>>>(hH, hL, pWH + (size_t)l * WID * WID, pWL + (size_t)l * WID * WID, WID,
                              nullptr, nullptr, nullptr, nullptr, 0,
                              bmlp + l * WID,
                              pfilm + l * 2 * WID, pfilm + l * 2 * WID + WID,
                              resid, 1,
                              gf, last ? nullptr : gH, last ? nullptr : gL, WID);
        float* tf = hf; hf = gf; gf = tf;
        __nv_bfloat16* th = hH; hH = gH; gH = th;
        __nv_bfloat16* tl = hL; hL = gL; gL = tl;
    }
    out_kernel<<<(NN * 32) / 256, 256>>>(hf, W_out, b_out, (float*)d_out);

    (void)in_sizes; (void)n_in; (void)out_size;
}